// round 2
// baseline (speedup 1.0000x reference)
#include <cuda_runtime.h>
#include <math.h>

// ---------------- problem constants ----------------
#define DIMC   192
#define HW     56
#define WSZ    7
#define SHIFT  3
#define NHEADS 6
#define HD     32
#define HIDDEN 768
#define BATCH  32
#define NTOK   (HW*HW)          // 3136
#define NWIN   64               // windows per image (8x8)
#define NBLKS  (BATCH*NWIN)     // 2048
#define NTOKW  49               // tokens per window

// ---------------- scratch (device global; no allocations) ----------------
__device__ float g_xattn[(size_t)BATCH * NTOK * DIMC];

// ---------------- helpers ----------------
__device__ __forceinline__ float warp_sum(float v){
#pragma unroll
    for (int o = 16; o; o >>= 1) v += __shfl_xor_sync(0xffffffffu, v, o);
    return v;
}
__device__ __forceinline__ float warp_max(float v){
#pragma unroll
    for (int o = 16; o; o >>= 1) v = fmaxf(v, __shfl_xor_sync(0xffffffffu, v, o));
    return v;
}
__device__ __forceinline__ float gelu_exact(float x){
    return 0.5f * x * (1.0f + erff(x * 0.70710678118654752440f));
}

// =====================================================================
// Kernel 1: shifted-window attention, one CTA per window.
//   gather(roll -3) -> LN1 -> per-head QKV -> softmax(QK^T)V -> proj
//   -> scatter(roll +3) into g_xattn
// =====================================================================
#define AT_THREADS 192
#define SX_STRIDE  196
#define QV_STRIDE  33
#define SSTRIDE    56
#define ATT_SMEM_FLOATS (50*SX_STRIDE + 49*SX_STRIDE + 3*49*QV_STRIDE + 49*SSTRIDE)
#define ATT_SMEM_BYTES  (ATT_SMEM_FLOATS * 4)

__global__ __launch_bounds__(AT_THREADS)
void attn_kernel(const float* __restrict__ x,
                 const float* __restrict__ qkv_w, const float* __restrict__ qkv_b,
                 const float* __restrict__ proj_w, const float* __restrict__ proj_b,
                 const float* __restrict__ g1, const float* __restrict__ be1)
{
    extern __shared__ float sm[];
    float* s_x = sm;                        // [50][196]  (row 49 = scratch pad)
    float* s_o = s_x + 50*SX_STRIDE;        // [49][196]
    float* s_q = s_o + 49*SX_STRIDE;        // [49][33]
    float* s_k = s_q + 49*QV_STRIDE;        // [49][33]
    float* s_v = s_k + 49*QV_STRIDE;        // [49][33]
    float* s_S = s_v + 49*QV_STRIDE;        // [49][56]

    const int t   = threadIdx.x;
    const int blk = blockIdx.x;
    const int b   = blk >> 6;
    const int win = blk & 63;
    const int wr  = win >> 3, wc = win & 7;

    const float* xb = x + (size_t)b * NTOK * DIMC;

    // --- gather with cyclic shift (roll -3,-3) ---
    for (int idx = t; idx < NTOKW*DIMC; idx += AT_THREADS){
        int row = idx / DIMC, c = idx - row*DIMC;
        int ti = row / WSZ, tj = row - ti*WSZ;
        int sr = wr*WSZ + ti + SHIFT; if (sr >= HW) sr -= HW;
        int sc = wc*WSZ + tj + SHIFT; if (sc >= HW) sc -= HW;
        s_x[row*SX_STRIDE + c] = xb[(sr*HW + sc)*DIMC + c];
    }
    __syncthreads();

    const int wid = t >> 5, lane = t & 31;

    // --- LN1 in place ---
    for (int r = wid; r < NTOKW; r += 6){
        float s = 0.f, s2 = 0.f;
#pragma unroll
        for (int c = lane; c < DIMC; c += 32){
            float v = s_x[r*SX_STRIDE + c]; s += v; s2 += v*v;
        }
        s = warp_sum(s); s2 = warp_sum(s2);
        float mu = s * (1.0f/DIMC);
        float rs = rsqrtf(s2*(1.0f/DIMC) - mu*mu + 1e-5f);
#pragma unroll
        for (int c = lane; c < DIMC; c += 32){
            float v = s_x[r*SX_STRIDE + c];
            s_x[r*SX_STRIDE + c] = (v - mu)*rs*g1[c] + be1[c];
        }
    }
    __syncthreads();

    // --- per-head attention ---
    for (int h = 0; h < NHEADS; h++){
        // QKV slice for this head: [49,192] @ [192,96]
        {
            const int col96 = t % 96;
            const int rg    = t / 96;           // 0 or 1
            const int which = col96 >> 5;       // 0=q 1=k 2=v
            const int d     = col96 & 31;
            const int wcol  = which*DIMC + h*HD + d;
            const float* wp = qkv_w + wcol;
            float acc[25];
#pragma unroll
            for (int i = 0; i < 25; i++) acc[i] = 0.f;
            const float* xr0 = s_x + (rg*25)*SX_STRIDE;
#pragma unroll 2
            for (int k = 0; k < DIMC; k++){
                float w = wp[k*(3*DIMC)];
#pragma unroll
                for (int i = 0; i < 25; i++)
                    acc[i] += xr0[i*SX_STRIDE + k] * w;   // rg=1,i=24 hits pad row 49 (discarded)
            }
            float bias = qkv_b[wcol];
            float* dst = (which == 0) ? s_q : (which == 1) ? s_k : s_v;
            const int r0 = rg*25;
#pragma unroll
            for (int i = 0; i < 25; i++){
                int r = r0 + i;
                if (r < NTOKW) dst[r*QV_STRIDE + d] = acc[i] + bias;
            }
        }
        __syncthreads();

        // S = scale * q k^T
        for (int idx = t; idx < NTOKW*NTOKW; idx += AT_THREADS){
            int i = idx / NTOKW, j = idx - i*NTOKW;
            const float* qi = s_q + i*QV_STRIDE;
            const float* kj = s_k + j*QV_STRIDE;
            float s = 0.f;
#pragma unroll
            for (int d2 = 0; d2 < HD; d2++) s += qi[d2]*kj[d2];
            s_S[i*SSTRIDE + j] = s * 0.17677669529663688110f;  // 1/sqrt(32)
        }
        __syncthreads();

        // row softmax
        for (int r = wid; r < NTOKW; r += 6){
            float v0 = (lane      < NTOKW) ? s_S[r*SSTRIDE + lane     ] : -1e30f;
            float v1 = (lane + 32 < NTOKW) ? s_S[r*SSTRIDE + lane + 32] : -1e30f;
            float m  = warp_max(fmaxf(v0, v1));
            float e0 = (lane      < NTOKW) ? __expf(v0 - m) : 0.f;
            float e1 = (lane + 32 < NTOKW) ? __expf(v1 - m) : 0.f;
            float inv = 1.0f / warp_sum(e0 + e1);
            if (lane      < NTOKW) s_S[r*SSTRIDE + lane     ] = e0 * inv;
            if (lane + 32 < NTOKW) s_S[r*SSTRIDE + lane + 32] = e1 * inv;
        }
        __syncthreads();

        // O = P @ v  -> columns [h*32, h*32+32) of s_o
        for (int idx = t; idx < NTOKW*HD; idx += AT_THREADS){
            int i = idx >> 5, d2 = idx & 31;
            const float* pi = s_S + i*SSTRIDE;
            const float* vd = s_v + d2;
            float s = 0.f;
#pragma unroll
            for (int j = 0; j < NTOKW; j++) s += pi[j] * vd[j*QV_STRIDE];
            s_o[i*SX_STRIDE + h*HD + d2] = s;
        }
        __syncthreads();
    }

    // --- proj [49,192]@[192,192] + scatter (roll +3,+3) ---
    {
        const int col = t;   // 192 threads == 192 cols
        float acc[NTOKW];
#pragma unroll
        for (int i = 0; i < NTOKW; i++) acc[i] = 0.f;
        const float* wp = proj_w + col;
#pragma unroll 2
        for (int k = 0; k < DIMC; k++){
            float w = wp[k*DIMC];
#pragma unroll
            for (int i = 0; i < NTOKW; i++)
                acc[i] += s_o[i*SX_STRIDE + k] * w;
        }
        float bias = proj_b[col];
        float* ob = g_xattn + (size_t)b * NTOK * DIMC;
#pragma unroll
        for (int i = 0; i < NTOKW; i++){
            int ti = i / WSZ, tj = i - ti*WSZ;
            int sr = wr*WSZ + ti + SHIFT; if (sr >= HW) sr -= HW;
            int sc = wc*WSZ + tj + SHIFT; if (sc >= HW) sc -= HW;
            ob[(sr*HW + sc)*DIMC + col] = acc[i] + bias;
        }
    }
}

// =====================================================================
// Kernel 2: fused MLP with residual.  out = x + gelu(LN2(x)@w1+b1)@w2 + b2
// 64 tokens/CTA, hidden processed in 12 chunks of 64 (never hits HBM).
// =====================================================================
#define ML_THREADS 256
#define TM 64
#define TH 64
#define XN_STRIDE 196
#define H_STRIDE  68
#define W2_STRIDE 196
#define MLP_SMEM_FLOATS (TM*XN_STRIDE + DIMC*TH + TM*H_STRIDE + TH*W2_STRIDE)
#define MLP_SMEM_BYTES  (MLP_SMEM_FLOATS * 4)

__global__ __launch_bounds__(ML_THREADS)
void mlp_kernel(const float* __restrict__ g2, const float* __restrict__ be2,
                const float* __restrict__ w1, const float* __restrict__ b1,
                const float* __restrict__ w2, const float* __restrict__ b2,
                float* __restrict__ out)
{
    extern __shared__ float sm[];
    float* s_xn = sm;                       // [64][196]
    float* s_w1 = s_xn + TM*XN_STRIDE;      // [192][64]
    float* s_h  = s_w1 + DIMC*TH;           // [64][68]
    float* s_w2 = s_h  + TM*H_STRIDE;       // [64][196]

    const int t = threadIdx.x;
    const size_t tok0 = (size_t)blockIdx.x * TM;
    const float* xb = g_xattn + tok0 * DIMC;

    // load tile
    for (int idx = t; idx < TM*DIMC; idx += ML_THREADS){
        int r = idx / DIMC, c = idx - r*DIMC;
        s_xn[r*XN_STRIDE + c] = xb[idx];
    }
    __syncthreads();

    const int wid = t >> 5, lane = t & 31;
    // LN2 in place
    for (int r = wid; r < TM; r += 8){
        float s = 0.f, s2 = 0.f;
#pragma unroll
        for (int c = lane; c < DIMC; c += 32){
            float v = s_xn[r*XN_STRIDE + c]; s += v; s2 += v*v;
        }
        s = warp_sum(s); s2 = warp_sum(s2);
        float mu = s * (1.0f/DIMC);
        float rs = rsqrtf(s2*(1.0f/DIMC) - mu*mu + 1e-5f);
#pragma unroll
        for (int c = lane; c < DIMC; c += 32){
            float v = s_xn[r*XN_STRIDE + c];
            s_xn[r*XN_STRIDE + c] = (v - mu)*rs*g2[c] + be2[c];
        }
    }

    const int tr = t >> 4, tc = t & 15;
    const int r1 = tr*4, c1 = tc*4;     // gemm1 micro-tile (4x4 of [64][64])
    const int ro = tr*4, co = tc*12;    // out micro-tile   (4x12 of [64][192])

    float acc[4][12];
#pragma unroll
    for (int i = 0; i < 4; i++)
#pragma unroll
        for (int j = 0; j < 12; j++) acc[i][j] = 0.f;

    for (int hc = 0; hc < HIDDEN; hc += TH){
        __syncthreads();   // prior chunk readers done (also orders LN writes on 1st iter)

        // stage weight chunks
        for (int idx = t; idx < DIMC*TH; idx += ML_THREADS){
            int k = idx >> 6, cc = idx & 63;
            s_w1[idx] = w1[(size_t)k*HIDDEN + hc + cc];
        }
        for (int idx = t; idx < TH*DIMC; idx += ML_THREADS){
            int k = idx / DIMC, c = idx - k*DIMC;
            s_w2[k*W2_STRIDE + c] = w2[(size_t)(hc + k)*DIMC + c];
        }
        __syncthreads();

        // GEMM1: h_tile[64][64] = xn @ w1_chunk
        float ha[4][4];
#pragma unroll
        for (int i = 0; i < 4; i++)
#pragma unroll
            for (int j = 0; j < 4; j++) ha[i][j] = 0.f;

#pragma unroll 2
        for (int k = 0; k < DIMC; k++){
            float4 bv = *(const float4*)(s_w1 + k*TH + c1);
            float bb[4] = {bv.x, bv.y, bv.z, bv.w};
            float aa[4];
#pragma unroll
            for (int i = 0; i < 4; i++) aa[i] = s_xn[(r1+i)*XN_STRIDE + k];
#pragma unroll
            for (int i = 0; i < 4; i++)
#pragma unroll
                for (int j = 0; j < 4; j++) ha[i][j] += aa[i]*bb[j];
        }
        // bias + exact GELU -> s_h
#pragma unroll
        for (int i = 0; i < 4; i++)
#pragma unroll
            for (int j = 0; j < 4; j++){
                float hv = ha[i][j] + b1[hc + c1 + j];
                s_h[(r1+i)*H_STRIDE + c1 + j] = gelu_exact(hv);
            }
        __syncthreads();

        // GEMM2: acc += h_tile @ w2_chunk
#pragma unroll 2
        for (int k = 0; k < TH; k++){
            float aa[4];
#pragma unroll
            for (int i = 0; i < 4; i++) aa[i] = s_h[(ro+i)*H_STRIDE + k];
            const float* wrow = s_w2 + k*W2_STRIDE + co;
            float4 b0 = *(const float4*)(wrow);
            float4 b1v = *(const float4*)(wrow + 4);
            float4 b2v = *(const float4*)(wrow + 8);
            float bb[12] = {b0.x,b0.y,b0.z,b0.w, b1v.x,b1v.y,b1v.z,b1v.w,
                            b2v.x,b2v.y,b2v.z,b2v.w};
#pragma unroll
            for (int i = 0; i < 4; i++)
#pragma unroll
                for (int j = 0; j < 12; j++) acc[i][j] += aa[i]*bb[j];
        }
    }
    __syncthreads();

    // stage raw acc to smem for a coalesced epilogue
#pragma unroll
    for (int i = 0; i < 4; i++)
#pragma unroll
        for (int j = 0; j < 12; j++)
            s_xn[(ro+i)*XN_STRIDE + co + j] = acc[i][j];
    __syncthreads();

    float* ob = out + tok0 * DIMC;
    for (int idx = t; idx < TM*DIMC; idx += ML_THREADS){
        int r = idx / DIMC, c = idx - r*DIMC;
        ob[idx] = s_xn[r*XN_STRIDE + c] + b2[c] + xb[idx];  // residual + bias
    }
}

// =====================================================================
// launch
// =====================================================================
extern "C" void kernel_launch(void* const* d_in, const int* in_sizes, int n_in,
                              void* d_out, int out_size)
{
    (void)in_sizes; (void)n_in; (void)out_size;
    const float* x      = (const float*)d_in[0];
    const float* qkv_w  = (const float*)d_in[1];
    const float* qkv_b  = (const float*)d_in[2];
    const float* proj_w = (const float*)d_in[3];
    const float* proj_b = (const float*)d_in[4];
    const float* g1     = (const float*)d_in[5];
    const float* be1    = (const float*)d_in[6];
    const float* g2     = (const float*)d_in[7];
    const float* be2    = (const float*)d_in[8];
    const float* w1     = (const float*)d_in[9];
    const float* b1     = (const float*)d_in[10];
    const float* w2     = (const float*)d_in[11];
    const float* b2     = (const float*)d_in[12];
    float* out = (float*)d_out;

    cudaFuncSetAttribute(attn_kernel, cudaFuncAttributeMaxDynamicSharedMemorySize, ATT_SMEM_BYTES);
    cudaFuncSetAttribute(mlp_kernel,  cudaFuncAttributeMaxDynamicSharedMemorySize, MLP_SMEM_BYTES);

    attn_kernel<<<NBLKS, AT_THREADS, ATT_SMEM_BYTES>>>(x, qkv_w, qkv_b, proj_w, proj_b, g1, be1);
    mlp_kernel<<<(BATCH*NTOK)/TM, ML_THREADS, MLP_SMEM_BYTES>>>(g2, be2, w1, b1, w2, b2, out);
}